// round 6
// baseline (speedup 1.0000x reference)
#include <cuda_runtime.h>
#include <math.h>

#define D 128
#define MAXN 100000
#define MAXE 600000
#define BM 64
#define LTHREADS 256
#define ASTRIDE 257   // odd stride: bank(row*257 + k) = (row + k) mod 32 -> conflict-free

typedef unsigned long long ull;

// ---------------- static device scratch (no allocs allowed) ----------------
__device__ float g_h0[(size_t)MAXN * D];
__device__ float g_h1[(size_t)MAXN * D];
__device__ float g_mean[(size_t)MAXN * D];
__device__ int   g_cnt[MAXN];
__device__ int   g_off[MAXN + 1];
__device__ int   g_cur[MAXN];
__device__ int   g_src[MAXE];

// ---------------- packed f32x2 helpers (Blackwell FFMA2) ----------------
__device__ __forceinline__ ull fma2(ull a, ull b, ull c) {
    ull d;
    asm("fma.rn.f32x2 %0, %1, %2, %3;" : "=l"(d) : "l"(a), "l"(b), "l"(c));
    return d;
}
__device__ __forceinline__ ull bcast2(float a) {
    ull d; unsigned int ai = __float_as_uint(a);
    asm("mov.b64 %0, {%1, %2};" : "=l"(d) : "r"(ai), "r"(ai));
    return d;
}
__device__ __forceinline__ void unpack2(ull v, float& lo, float& hi) {
    unsigned int l, h;
    asm("mov.b64 {%0, %1}, %2;" : "=r"(l), "=r"(h) : "l"(v));
    lo = __uint_as_float(l); hi = __uint_as_float(h);
}

// ---------------- CSR construction ----------------
__global__ void count_kernel(const int* __restrict__ dst, int* cnt, int E) {
    int e = blockIdx.x * blockDim.x + threadIdx.x;
    if (e < E) atomicAdd(&cnt[dst[e]], 1);
}

__global__ void scan_kernel(const int* __restrict__ cnt, int* off, int* cur, int N) {
    __shared__ int part[1024];
    int t = threadIdx.x;
    int chunk = (N + 1023) / 1024;
    int s = t * chunk;
    int e = min(s + chunk, N);
    int sum = 0;
    for (int i = s; i < e; ++i) sum += cnt[i];
    part[t] = sum;
    __syncthreads();
    for (int d = 1; d < 1024; d <<= 1) {
        int v = (t >= d) ? part[t - d] : 0;
        __syncthreads();
        part[t] += v;
        __syncthreads();
    }
    int run = (t == 0) ? 0 : part[t - 1];
    for (int i = s; i < e; ++i) {
        off[i] = run;
        cur[i] = run;
        run += cnt[i];
    }
    if (t == 1023) off[N] = part[1023];
}

__global__ void fill_kernel(const int* __restrict__ src, const int* __restrict__ dst,
                            int* cur, int* out, int E) {
    int e = blockIdx.x * blockDim.x + threadIdx.x;
    if (e < E) {
        int d = dst[e];
        int pos = atomicAdd(&cur[d], 1);
        out[pos] = src[e];
    }
}

// ---------------- aggregation: warp-per-node CSR mean (high occupancy) -----
__global__ __launch_bounds__(256) void agg_kernel(
    const float* __restrict__ h, float* __restrict__ mean,
    const int* __restrict__ off, const int* __restrict__ srcs, int N)
{
    int gw = (blockIdx.x * 256 + threadIdx.x) >> 5;   // global warp = node
    int lane = threadIdx.x & 31;
    if (gw >= N) return;

    int s = __ldg(&off[gw]);
    int e = __ldg(&off[gw + 1]);

    float4 acc = make_float4(0.f, 0.f, 0.f, 0.f);
    int k = s;
    for (; k + 4 <= e; k += 4) {
        int u0 = __ldg(&srcs[k]);
        int u1 = __ldg(&srcs[k + 1]);
        int u2 = __ldg(&srcs[k + 2]);
        int u3 = __ldg(&srcs[k + 3]);
        float4 a = __ldg((const float4*)(h + (size_t)u0 * D + lane * 4));
        float4 b = __ldg((const float4*)(h + (size_t)u1 * D + lane * 4));
        float4 c = __ldg((const float4*)(h + (size_t)u2 * D + lane * 4));
        float4 d = __ldg((const float4*)(h + (size_t)u3 * D + lane * 4));
        acc.x += (a.x + b.x) + (c.x + d.x);
        acc.y += (a.y + b.y) + (c.y + d.y);
        acc.z += (a.z + b.z) + (c.z + d.z);
        acc.w += (a.w + b.w) + (c.w + d.w);
    }
    for (; k < e; ++k) {
        int u = __ldg(&srcs[k]);
        float4 a = __ldg((const float4*)(h + (size_t)u * D + lane * 4));
        acc.x += a.x; acc.y += a.y; acc.z += a.z; acc.w += a.w;
    }
    float ic = 1.0f / (float)max(e - s, 1);
    acc.x *= ic; acc.y *= ic; acc.z *= ic; acc.w *= ic;
    *(float4*)(mean + (size_t)gw * D + lane * 4) = acc;
}

// ---------------- dense GEMM: C = relu([mean|h] @ [Wl;Wr] + b) -------------
// Warp w computes a 64-row x 16-col tile (cols w*16..w*16+16).
// Per k: 4 uniform-address LDG.128 of W (64B broadcast across lanes, reused
// by 64 rows) + 2 conflict-free scalar LDS of A + 16 FFMA2.
__global__ __launch_bounds__(LTHREADS, 2) void gemm_kernel(
    const float* __restrict__ mean, const float* __restrict__ h_in,
    float* __restrict__ h_out,
    const float* __restrict__ Wl, const float* __restrict__ Wr,
    const float* __restrict__ bias, int N)
{
    extern __shared__ float As[];   // [BM][ASTRIDE]: cols 0..127 = mean, 128..255 = h

    const int t = threadIdx.x;
    const int lane = t & 31;
    const int w = t >> 5;           // warp id = column group
    const int row0 = blockIdx.x * BM;

    // ---- stage [mean | h] rows: float4 gmem loads, SCALAR smem stores
    //      (ASTRIDE=257 is odd -> float4 STS would be misaligned) ----
    for (int i = t; i < BM * (D / 4); i += LTHREADS) {
        int r = i >> 5;
        int c4 = (i & 31) << 2;
        int gr = row0 + r;
        float4 m  = make_float4(0.f, 0.f, 0.f, 0.f);
        float4 hv = make_float4(0.f, 0.f, 0.f, 0.f);
        if (gr < N) {
            m  = __ldg((const float4*)(mean + (size_t)gr * D + c4));
            hv = __ldg((const float4*)(h_in + (size_t)gr * D + c4));
        }
        float* pm = &As[r * ASTRIDE + c4];
        pm[0] = m.x;  pm[1] = m.y;  pm[2] = m.z;  pm[3] = m.w;
        float* ph = &As[r * ASTRIDE + D + c4];
        ph[0] = hv.x; ph[1] = hv.y; ph[2] = hv.z; ph[3] = hv.w;
    }
    __syncthreads();

    ull acc[2][8];    // [row group: lane / lane+32][8 col pairs]
#pragma unroll
    for (int i = 0; i < 2; ++i)
#pragma unroll
        for (int j = 0; j < 8; ++j) acc[i][j] = 0ull;

#pragma unroll 1
    for (int pass = 0; pass < 2; ++pass) {
        // weight pointer for this warp's 16 cols, in f32x2 pairs
        const ull* __restrict__ Wp = (const ull*)(pass ? Wr : Wl) + w * 8;
        const float* __restrict__ A0 = As + (size_t)lane * ASTRIDE + pass * D;
        const float* __restrict__ A1 = A0 + 32 * ASTRIDE;

#pragma unroll 2
        for (int k = 0; k < D; ++k) {
            ulonglong2 wa = __ldg((const ulonglong2*)(Wp));
            ulonglong2 wb = __ldg((const ulonglong2*)(Wp + 2));
            ulonglong2 wc = __ldg((const ulonglong2*)(Wp + 4));
            ulonglong2 wd = __ldg((const ulonglong2*)(Wp + 6));
            Wp += D / 2;
            ull w8[8] = {wa.x, wa.y, wb.x, wb.y, wc.x, wc.y, wd.x, wd.y};

            ull a0 = bcast2(A0[k]);
            ull a1 = bcast2(A1[k]);

#pragma unroll
            for (int j = 0; j < 8; ++j) {
                acc[0][j] = fma2(a0, w8[j], acc[0][j]);
                acc[1][j] = fma2(a1, w8[j], acc[1][j]);
            }
        }
    }

    // ---- epilogue: bias + relu + store (16 cols, rows lane & lane+32) ----
    const float* bp = bias + w * 16;
    float bl[16];
#pragma unroll
    for (int c = 0; c < 16; ++c) bl[c] = __ldg(bp + c);

#pragma unroll
    for (int i = 0; i < 2; ++i) {
        int gr = row0 + lane + 32 * i;
        if (gr >= N) continue;
        float o[16];
#pragma unroll
        for (int j = 0; j < 8; ++j) unpack2(acc[i][j], o[2 * j], o[2 * j + 1]);
#pragma unroll
        for (int c = 0; c < 16; ++c) o[c] = fmaxf(o[c] + bl[c], 0.0f);
        float* outp = h_out + (size_t)gr * D + w * 16;
#pragma unroll
        for (int q = 0; q < 4; ++q)
            *(float4*)(outp + 4 * q) = make_float4(o[4 * q], o[4 * q + 1],
                                                   o[4 * q + 2], o[4 * q + 3]);
    }
}

// ---------------- pooled sum (sorted batch) + sigmoid head -----------------
__global__ void pool_head_kernel(const float* __restrict__ h, const int* __restrict__ batch,
                                 const float* __restrict__ Wro, const float* __restrict__ bro,
                                 float* __restrict__ out, int N)
{
    __shared__ int bounds[2];
    __shared__ float red[4];
    int g = blockIdx.x;
    int t = threadIdx.x;   // 128 threads, t = feature column

    if (t < 2) {
        int target = g + t;
        int lo = 0, hi = N;
        while (lo < hi) {
            int mid = (lo + hi) >> 1;
            if (batch[mid] < target) lo = mid + 1; else hi = mid;
        }
        bounds[t] = lo;
    }
    __syncthreads();
    int s = bounds[0], e = bounds[1];

    float sum = 0.0f;
    for (int v = s; v < e; ++v) sum += h[(size_t)v * D + t];
    float val = sum * __ldg(&Wro[t]);
#pragma unroll
    for (int o = 16; o > 0; o >>= 1) val += __shfl_xor_sync(0xffffffff, val, o);
    if ((t & 31) == 0) red[t >> 5] = val;
    __syncthreads();
    if (t == 0) {
        float z = red[0] + red[1] + red[2] + red[3] + __ldg(bro);
        out[g] = 1.0f / (1.0f + expf(-z));
    }
}

// ---------------- launcher ----------------
extern "C" void kernel_launch(void* const* d_in, const int* in_sizes, int n_in,
                              void* d_out, int out_size)
{
    const float* x     = (const float*)d_in[0];
    const int*   ei    = (const int*)d_in[1];
    const int*   batch = (const int*)d_in[2];
    const float* Wl1 = (const float*)d_in[3];
    const float* Wr1 = (const float*)d_in[4];
    const float* b1  = (const float*)d_in[5];
    const float* Wl2 = (const float*)d_in[6];
    const float* Wr2 = (const float*)d_in[7];
    const float* b2  = (const float*)d_in[8];
    const float* Wl3 = (const float*)d_in[9];
    const float* Wr3 = (const float*)d_in[10];
    const float* b3  = (const float*)d_in[11];
    const float* Wro = (const float*)d_in[12];
    const float* bro = (const float*)d_in[13];
    float* out = (float*)d_out;

    int N = in_sizes[0] / D;
    int E = in_sizes[1] / 2;
    int G = out_size;

    float *h0, *h1, *mn;
    int *cnt, *off, *cur, *srcs;
    cudaGetSymbolAddress((void**)&h0,   g_h0);
    cudaGetSymbolAddress((void**)&h1,   g_h1);
    cudaGetSymbolAddress((void**)&mn,   g_mean);
    cudaGetSymbolAddress((void**)&cnt,  g_cnt);
    cudaGetSymbolAddress((void**)&off,  g_off);
    cudaGetSymbolAddress((void**)&cur,  g_cur);
    cudaGetSymbolAddress((void**)&srcs, g_src);

    const int* src_arr = ei;
    const int* dst_arr = ei + E;

    // CSR build
    cudaMemsetAsync(cnt, 0, (size_t)N * sizeof(int));
    count_kernel<<<(E + 255) / 256, 256>>>(dst_arr, cnt, E);
    scan_kernel<<<1, 1024>>>(cnt, off, cur, N);
    fill_kernel<<<(E + 255) / 256, 256>>>(src_arr, dst_arr, cur, srcs, E);

    int smem = BM * ASTRIDE * sizeof(float);
    cudaFuncSetAttribute((const void*)gemm_kernel,
                         cudaFuncAttributeMaxDynamicSharedMemorySize, smem);
    int gblocks = (N + BM - 1) / BM;
    int ablocks = (N * 32 + 255) / 256;   // warp per node

    // layer 1
    agg_kernel<<<ablocks, 256>>>(x, mn, off, srcs, N);
    gemm_kernel<<<gblocks, LTHREADS, smem>>>(mn, x, h0, Wl1, Wr1, b1, N);
    // layer 2
    agg_kernel<<<ablocks, 256>>>(h0, mn, off, srcs, N);
    gemm_kernel<<<gblocks, LTHREADS, smem>>>(mn, h0, h1, Wl2, Wr2, b2, N);
    // layer 3
    agg_kernel<<<ablocks, 256>>>(h1, mn, off, srcs, N);
    gemm_kernel<<<gblocks, LTHREADS, smem>>>(mn, h1, h0, Wl3, Wr3, b3, N);

    // pooling + head
    pool_head_kernel<<<G, D>>>(h0, batch, Wro, bro, out, N);
}

// round 8
// speedup vs baseline: 1.9974x; 1.9974x over previous
#include <cuda_runtime.h>
#include <cuda_bf16.h>
#include <math.h>
#include <stdint.h>

#define D 128
#define MAXN 100000
#define MAXE 600000

// ---------------- static device scratch (no allocs allowed) ----------------
__device__ float g_h0[(size_t)MAXN * D];
__device__ float g_h1[(size_t)MAXN * D];
__device__ float g_mean[(size_t)MAXN * D];
__device__ int   g_cnt[MAXN];
__device__ int   g_off[MAXN + 1];
__device__ int   g_cur[MAXN];
__device__ int   g_src[MAXE];
// 12 pre-swizzled weight images: (3 layers x {Wl,Wr} x {hi,lo}), each 128k x 128n bf16
__device__ __nv_bfloat16 g_wimg[12 * 16384];

// ---------------- warp-mma helpers (classic HMMA path, generic PTX) --------
__device__ __forceinline__ uint32_t smem_u32(const void* p) {
    uint32_t a;
    asm("{ .reg .u64 t; cvta.to.shared.u64 t, %1; cvt.u32.u64 %0, t; }" : "=r"(a) : "l"(p));
    return a;
}
__device__ __forceinline__ void ldsm_x4(uint32_t* r, uint32_t addr) {
    asm volatile("ldmatrix.sync.aligned.m8n8.x4.shared.b16 {%0,%1,%2,%3}, [%4];"
                 : "=r"(r[0]), "=r"(r[1]), "=r"(r[2]), "=r"(r[3]) : "r"(addr));
}
__device__ __forceinline__ void ldsm_x4_t(uint32_t* r, uint32_t addr) {
    asm volatile("ldmatrix.sync.aligned.m8n8.x4.trans.shared.b16 {%0,%1,%2,%3}, [%4];"
                 : "=r"(r[0]), "=r"(r[1]), "=r"(r[2]), "=r"(r[3]) : "r"(addr));
}
__device__ __forceinline__ void mma_bf16(float* c, const uint32_t* a, const uint32_t* b) {
    asm volatile(
        "mma.sync.aligned.m16n8k16.row.col.f32.bf16.bf16.f32 "
        "{%0,%1,%2,%3}, {%4,%5,%6,%7}, {%8,%9}, {%0,%1,%2,%3};"
        : "+f"(c[0]), "+f"(c[1]), "+f"(c[2]), "+f"(c[3])
        : "r"(a[0]), "r"(a[1]), "r"(a[2]), "r"(a[3]), "r"(b[0]), "r"(b[1]));
}

// ---------------- CSR construction ----------------
__global__ void count_kernel(const int* __restrict__ dst, int* cnt, int E) {
    int e = blockIdx.x * blockDim.x + threadIdx.x;
    if (e < E) atomicAdd(&cnt[dst[e]], 1);
}

__global__ void scan_kernel(const int* __restrict__ cnt, int* off, int* cur, int N) {
    __shared__ int part[1024];
    int t = threadIdx.x;
    int chunk = (N + 1023) / 1024;
    int s = t * chunk;
    int e = min(s + chunk, N);
    int sum = 0;
    for (int i = s; i < e; ++i) sum += cnt[i];
    part[t] = sum;
    __syncthreads();
    for (int d = 1; d < 1024; d <<= 1) {
        int v = (t >= d) ? part[t - d] : 0;
        __syncthreads();
        part[t] += v;
        __syncthreads();
    }
    int run = (t == 0) ? 0 : part[t - 1];
    for (int i = s; i < e; ++i) {
        off[i] = run;
        cur[i] = run;
        run += cnt[i];
    }
    if (t == 1023) off[N] = part[1023];
}

__global__ void fill_kernel(const int* __restrict__ src, const int* __restrict__ dst,
                            int* cur, int* out, int E) {
    int e = blockIdx.x * blockDim.x + threadIdx.x;
    if (e < E) {
        int d = dst[e];
        int pos = atomicAdd(&cur[d], 1);
        out[pos] = src[e];
    }
}

// ---------------- aggregation: warp-per-node CSR mean ----------------------
__global__ __launch_bounds__(256) void agg_kernel(
    const float* __restrict__ h, float* __restrict__ mean,
    const int* __restrict__ off, const int* __restrict__ srcs, int N)
{
    int gw = (blockIdx.x * 256 + threadIdx.x) >> 5;
    int lane = threadIdx.x & 31;
    if (gw >= N) return;

    int s = __ldg(&off[gw]);
    int e = __ldg(&off[gw + 1]);

    float4 acc = make_float4(0.f, 0.f, 0.f, 0.f);
    int k = s;
    for (; k + 4 <= e; k += 4) {
        int u0 = __ldg(&srcs[k]);
        int u1 = __ldg(&srcs[k + 1]);
        int u2 = __ldg(&srcs[k + 2]);
        int u3 = __ldg(&srcs[k + 3]);
        float4 a = __ldg((const float4*)(h + (size_t)u0 * D + lane * 4));
        float4 b = __ldg((const float4*)(h + (size_t)u1 * D + lane * 4));
        float4 c = __ldg((const float4*)(h + (size_t)u2 * D + lane * 4));
        float4 d = __ldg((const float4*)(h + (size_t)u3 * D + lane * 4));
        acc.x += (a.x + b.x) + (c.x + d.x);
        acc.y += (a.y + b.y) + (c.y + d.y);
        acc.z += (a.z + b.z) + (c.z + d.z);
        acc.w += (a.w + b.w) + (c.w + d.w);
    }
    for (; k < e; ++k) {
        int u = __ldg(&srcs[k]);
        float4 a = __ldg((const float4*)(h + (size_t)u * D + lane * 4));
        acc.x += a.x; acc.y += a.y; acc.z += a.z; acc.w += a.w;
    }
    float ic = 1.0f / (float)max(e - s, 1);
    acc.x *= ic; acc.y *= ic; acc.z *= ic; acc.w *= ic;
    *(float4*)(mean + (size_t)gw * D + lane * 4) = acc;
}

// ---------------- weight prep: fp32 W[k][n] -> swizzled bf16 hi/lo images --
// Image layout (per k-chunk of 64): byte = (k>>6)*16384 + (k&63)*256
//                                        + (((n>>3) ^ (k&7)) << 4) + (n&7)*2
__global__ void prep_w_kernel(const float* __restrict__ W,
                              __nv_bfloat16* __restrict__ hi,
                              __nv_bfloat16* __restrict__ lo)
{
    int i = blockIdx.x * 256 + threadIdx.x;
    if (i >= 128 * 128) return;
    int k = i >> 7;
    int n = i & 127;
    float x = __ldg(W + k * 128 + n);
    __nv_bfloat16 h = __float2bfloat16(x);
    float l = x - __bfloat162float(h);
    uint32_t byte = (uint32_t)(k >> 6) * 16384u + (uint32_t)(k & 63) * 256u
                  + ((uint32_t)((n >> 3) ^ (k & 7)) << 4) + (uint32_t)(n & 7) * 2u;
    hi[byte >> 1] = h;
    lo[byte >> 1] = __float2bfloat16(l);
}

// ---------------- HMMA GEMM: relu([mean|h] @ [Wl;Wr] + b), bf16 split-3 ----
// CTA: 128 rows x 128 cols, K=256 in 4 chunks of 64. 8 warps, warp = 32x64.
#define GT 256
#define SM_AHI 0
#define SM_ALO 16384
#define SM_WHI 32768
#define SM_WLO 49152
#define SM_TOT 65536

__global__ __launch_bounds__(GT, 2) void gemm_mma_kernel(
    const float* __restrict__ mean, const float* __restrict__ h_in,
    float* __restrict__ h_out,
    const __nv_bfloat16* __restrict__ wlhi, const __nv_bfloat16* __restrict__ wllo,
    const __nv_bfloat16* __restrict__ wrhi, const __nv_bfloat16* __restrict__ wrlo,
    const float* __restrict__ bias, int N)
{
    extern __shared__ char smem[];
    const uint32_t sb = smem_u32(smem);
    const int t = threadIdx.x;
    const int lane = t & 31;
    const int w = t >> 5;
    const int wrow = (w & 3) * 32;       // warp row offset in CTA tile
    const int wcol = (w >> 2) * 64;      // warp col offset
    const int row0 = blockIdx.x * 128;

    const float* asrc[2] = {mean, h_in};
    const __nv_bfloat16* whis[2] = {wlhi, wrhi};
    const __nv_bfloat16* wlos[2] = {wllo, wrlo};

    float C[64];                          // [mf 2][nf 8][4]
#pragma unroll
    for (int i = 0; i < 64; ++i) C[i] = 0.f;

    // ldmatrix lane-address selectors (canonical x4 pattern)
    const int rsel = (lane & 7) + ((lane >> 3) & 1) * 8;
    const int usel = lane >> 4;   // 0 or 1: second 8-col (16B) unit

    for (int chunk = 0; chunk < 4; ++chunk) {
        const int mat = chunk >> 1;   // 0: mean@Wl, 1: h@Wr
        const int kh  = chunk & 1;    // k-half within the 128-wide matrix

        // ---- stage A chunk (128 rows x 64 k) as bf16 hi/lo, swizzled ----
        const float* As = asrc[mat];
        for (int p = t; p < 128 * 32; p += GT) {
            int r  = p >> 5;
            int kp = (p & 31) * 2;
            int gr = row0 + r;
            float x0 = 0.f, x1 = 0.f;
            if (gr < N) {
                float2 v = *(const float2*)(As + (size_t)gr * D + kh * 64 + kp);
                x0 = v.x; x1 = v.y;
            }
            __nv_bfloat16 h0 = __float2bfloat16(x0);
            __nv_bfloat16 h1 = __float2bfloat16(x1);
            __nv_bfloat162 hp; hp.x = h0; hp.y = h1;
            __nv_bfloat162 lp;
            lp.x = __float2bfloat16(x0 - __bfloat162float(h0));
            lp.y = __float2bfloat16(x1 - __bfloat162float(h1));
            uint32_t byte = (uint32_t)r * 128u
                          + ((uint32_t)((kp >> 3) ^ (r & 7)) << 4) + (uint32_t)(kp & 7) * 2u;
            *(__nv_bfloat162*)(smem + SM_AHI + byte) = hp;
            *(__nv_bfloat162*)(smem + SM_ALO + byte) = lp;
        }

        // ---- stage W chunk: linear copy of pre-swizzled 16KB half-images ----
        const int4* hsrc = (const int4*)(whis[mat]) + kh * 1024;
        const int4* lsrc = (const int4*)(wlos[mat]) + kh * 1024;
        for (int i = t; i < 1024; i += GT) {
            ((int4*)(smem + SM_WHI))[i] = __ldg(hsrc + i);
            ((int4*)(smem + SM_WLO))[i] = __ldg(lsrc + i);
        }
        __syncthreads();

        // ---- compute: 4 k-steps of 16 ----
#pragma unroll
        for (int ks = 0; ks < 4; ++ks) {
            const int k0 = ks * 16;
            uint32_t ah[2][4], al[2][4];
#pragma unroll
            for (int mf = 0; mf < 2; ++mf) {
                int row = wrow + mf * 16 + rsel;
                uint32_t unit = (uint32_t)(((k0 >> 3) + usel) ^ (lane & 7));
                uint32_t aaddr = sb + SM_AHI + (uint32_t)row * 128u + (unit << 4);
                ldsm_x4(ah[mf], aaddr);
                ldsm_x4(al[mf], aaddr + 16384u);
            }
#pragma unroll
            for (int nq = 0; nq < 4; ++nq) {
                const int n0 = wcol + nq * 16;
                int krow = k0 + rsel;
                uint32_t unit = (uint32_t)(((n0 >> 3) + usel) ^ (lane & 7));
                uint32_t baddr = sb + SM_WHI + (uint32_t)krow * 256u + (unit << 4);
                uint32_t bh[4], bl[4];
                ldsm_x4_t(bh, baddr);
                ldsm_x4_t(bl, baddr + 16384u);
#pragma unroll
                for (int mf = 0; mf < 2; ++mf) {
                    float* c0 = &C[((mf * 8 + nq * 2) << 2)];
                    float* c1 = &C[((mf * 8 + nq * 2 + 1) << 2)];
                    mma_bf16(c0, ah[mf], bh);
                    mma_bf16(c0, ah[mf], bl);
                    mma_bf16(c0, al[mf], bh);
                    mma_bf16(c1, ah[mf], bh + 2);
                    mma_bf16(c1, ah[mf], bl + 2);
                    mma_bf16(c1, al[mf], bh + 2);
                }
            }
        }
        __syncthreads();
    }

    // ---- epilogue: bias + relu + store ----
#pragma unroll
    for (int mf = 0; mf < 2; ++mf) {
        int rlo = row0 + wrow + mf * 16 + (lane >> 2);
#pragma unroll
        for (int nf = 0; nf < 8; ++nf) {
            int col = wcol + nf * 8 + (lane & 3) * 2;
            float b0 = __ldg(bias + col);
            float b1 = __ldg(bias + col + 1);
            const float* c = &C[((mf * 8 + nf) << 2)];
            if (rlo < N) {
                float2 v;
                v.x = fmaxf(c[0] + b0, 0.f);
                v.y = fmaxf(c[1] + b1, 0.f);
                *(float2*)(h_out + (size_t)rlo * D + col) = v;
            }
            int rhi = rlo + 8;
            if (rhi < N) {
                float2 v;
                v.x = fmaxf(c[2] + b0, 0.f);
                v.y = fmaxf(c[3] + b1, 0.f);
                *(float2*)(h_out + (size_t)rhi * D + col) = v;
            }
        }
    }
}

// ---------------- pooled sum (sorted batch) + sigmoid head -----------------
__global__ void pool_head_kernel(const float* __restrict__ h, const int* __restrict__ batch,
                                 const float* __restrict__ Wro, const float* __restrict__ bro,
                                 float* __restrict__ out, int N)
{
    __shared__ int bounds[2];
    __shared__ float red[4];
    int g = blockIdx.x;
    int t = threadIdx.x;

    if (t < 2) {
        int target = g + t;
        int lo = 0, hi = N;
        while (lo < hi) {
            int mid = (lo + hi) >> 1;
            if (batch[mid] < target) lo = mid + 1; else hi = mid;
        }
        bounds[t] = lo;
    }
    __syncthreads();
    int s = bounds[0], e = bounds[1];

    float sum = 0.0f;
    for (int v = s; v < e; ++v) sum += h[(size_t)v * D + t];
    float val = sum * __ldg(&Wro[t]);
#pragma unroll
    for (int o = 16; o > 0; o >>= 1) val += __shfl_xor_sync(0xffffffff, val, o);
    if ((t & 31) == 0) red[t >> 5] = val;
    __syncthreads();
    if (t == 0) {
        float z = red[0] + red[1] + red[2] + red[3] + __ldg(bro);
        out[g] = 1.0f / (1.0f + expf(-z));
    }
}

// ---------------- launcher ----------------
extern "C" void kernel_launch(void* const* d_in, const int* in_sizes, int n_in,
                              void* d_out, int out_size)
{
    const float* x     = (const float*)d_in[0];
    const int*   ei    = (const int*)d_in[1];
    const int*   batch = (const int*)d_in[2];
    const float* Wmat[6] = {(const float*)d_in[3], (const float*)d_in[4],   // Wl1, Wr1
                            (const float*)d_in[6], (const float*)d_in[7],   // Wl2, Wr2
                            (const float*)d_in[9], (const float*)d_in[10]}; // Wl3, Wr3
    const float* b1  = (const float*)d_in[5];
    const float* b2  = (const float*)d_in[8];
    const float* b3  = (const float*)d_in[11];
    const float* Wro = (const float*)d_in[12];
    const float* bro = (const float*)d_in[13];
    float* out = (float*)d_out;

    int N = in_sizes[0] / D;
    int E = in_sizes[1] / 2;
    int G = out_size;

    float *h0, *h1, *mn;
    int *cnt, *off, *cur, *srcs;
    __nv_bfloat16* wimg;
    cudaGetSymbolAddress((void**)&h0,   g_h0);
    cudaGetSymbolAddress((void**)&h1,   g_h1);
    cudaGetSymbolAddress((void**)&mn,   g_mean);
    cudaGetSymbolAddress((void**)&cnt,  g_cnt);
    cudaGetSymbolAddress((void**)&off,  g_off);
    cudaGetSymbolAddress((void**)&cur,  g_cur);
    cudaGetSymbolAddress((void**)&srcs, g_src);
    cudaGetSymbolAddress((void**)&wimg, g_wimg);

    const int* src_arr = ei;
    const int* dst_arr = ei + E;

    // weight prep: 6 matrices -> hi/lo swizzled images
    for (int m = 0; m < 6; ++m) {
        __nv_bfloat16* hi = wimg + (size_t)(2 * m) * 16384;
        __nv_bfloat16* lo = wimg + (size_t)(2 * m + 1) * 16384;
        prep_w_kernel<<<64, 256>>>(Wmat[m], hi, lo);
    }

    // CSR build
    cudaMemsetAsync(cnt, 0, (size_t)N * sizeof(int));
    count_kernel<<<(E + 255) / 256, 256>>>(dst_arr, cnt, E);
    scan_kernel<<<1, 1024>>>(cnt, off, cur, N);
    fill_kernel<<<(E + 255) / 256, 256>>>(src_arr, dst_arr, cur, srcs, E);

    cudaFuncSetAttribute((const void*)gemm_mma_kernel,
                         cudaFuncAttributeMaxDynamicSharedMemorySize, SM_TOT);
    int gblocks = (N + 127) / 128;
    int ablocks = (N * 32 + 255) / 256;

    __nv_bfloat16* im = wimg;
    // layer 1
    agg_kernel<<<ablocks, 256>>>(x, mn, off, srcs, N);
    gemm_mma_kernel<<<gblocks, GT, SM_TOT>>>(mn, x, h0,
        im + 0 * 16384, im + 1 * 16384, im + 2 * 16384, im + 3 * 16384, b1, N);
    // layer 2
    agg_kernel<<<ablocks, 256>>>(h0, mn, off, srcs, N);
    gemm_mma_kernel<<<gblocks, GT, SM_TOT>>>(mn, h0, h1,
        im + 4 * 16384, im + 5 * 16384, im + 6 * 16384, im + 7 * 16384, b2, N);
    // layer 3
    agg_kernel<<<ablocks, 256>>>(h1, mn, off, srcs, N);
    gemm_mma_kernel<<<gblocks, GT, SM_TOT>>>(mn, h1, h0,
        im + 8 * 16384, im + 9 * 16384, im + 10 * 16384, im + 11 * 16384, b3, N);

    // pooling + head
    pool_head_kernel<<<G, D>>>(h0, batch, Wro, bro, out, N);
}

// round 9
// speedup vs baseline: 2.2295x; 1.1162x over previous
#include <cuda_runtime.h>
#include <cuda_bf16.h>
#include <math.h>
#include <stdint.h>

#define D 128
#define MAXN 100000
#define MAXE 600000
#define NBLK 782   // ceil(MAXN/128)

// ---------------- static device scratch (no allocs allowed) ----------------
__device__ float g_h0[(size_t)MAXN * D];
__device__ float g_h1[(size_t)MAXN * D];
__device__ int   g_cnt[MAXN];
__device__ int   g_off[MAXN + 1];
__device__ int   g_cur[MAXN];
__device__ int   g_src[MAXE];
// 12 pre-swizzled weight images: (3 layers x {Wl,Wr} x {hi,lo}), each 128k x 128n bf16
__device__ __nv_bfloat16 g_wimg[12 * 16384];
// A-operand images (pre-swizzled, per 128-row block: 128 rows x 2 k-halves x 128B)
__device__ __nv_bfloat16 g_mimg_h[(size_t)NBLK * 16384];
__device__ __nv_bfloat16 g_mimg_l[(size_t)NBLK * 16384];
__device__ __nv_bfloat16 g_ximg_h[(size_t)NBLK * 16384];
__device__ __nv_bfloat16 g_ximg_l[(size_t)NBLK * 16384];
__device__ __nv_bfloat16 g_yimg_h[(size_t)NBLK * 16384];
__device__ __nv_bfloat16 g_yimg_l[(size_t)NBLK * 16384];

// ---------------- helpers ----------------
__device__ __forceinline__ uint32_t smem_u32(const void* p) {
    uint32_t a;
    asm("{ .reg .u64 t; cvta.to.shared.u64 t, %1; cvt.u32.u64 %0, t; }" : "=r"(a) : "l"(p));
    return a;
}
__device__ __forceinline__ void cp16(uint32_t s, const void* g) {
    asm volatile("cp.async.cg.shared.global [%0], [%1], 16;" :: "r"(s), "l"(g));
}
__device__ __forceinline__ void ldsm_x4(uint32_t* r, uint32_t addr) {
    asm volatile("ldmatrix.sync.aligned.m8n8.x4.shared.b16 {%0,%1,%2,%3}, [%4];"
                 : "=r"(r[0]), "=r"(r[1]), "=r"(r[2]), "=r"(r[3]) : "r"(addr));
}
__device__ __forceinline__ void ldsm_x4_t(uint32_t* r, uint32_t addr) {
    asm volatile("ldmatrix.sync.aligned.m8n8.x4.trans.shared.b16 {%0,%1,%2,%3}, [%4];"
                 : "=r"(r[0]), "=r"(r[1]), "=r"(r[2]), "=r"(r[3]) : "r"(addr));
}
__device__ __forceinline__ void mma_bf16(float* c, const uint32_t* a, const uint32_t* b) {
    asm volatile(
        "mma.sync.aligned.m16n8k16.row.col.f32.bf16.bf16.f32 "
        "{%0,%1,%2,%3}, {%4,%5,%6,%7}, {%8,%9}, {%0,%1,%2,%3};"
        : "+f"(c[0]), "+f"(c[1]), "+f"(c[2]), "+f"(c[3])
        : "r"(a[0]), "r"(a[1]), "r"(a[2]), "r"(a[3]), "r"(b[0]), "r"(b[1]));
}

// A-image byte offset: block, k-half, row (0..127), k within half (0..63)
__device__ __forceinline__ uint32_t a_img_byte(int b, int kh, int r, int kp) {
    return (uint32_t)b * 32768u + (uint32_t)kh * 16384u + (uint32_t)r * 128u
         + ((uint32_t)((kp >> 3) ^ (r & 7)) << 4) + ((uint32_t)(kp & 7) << 1);
}

// store 4 consecutive cols (col0 = 4*lane) of a node as bf16 hi/lo pairs
__device__ __forceinline__ void store_a_quad(__nv_bfloat16* ih, __nv_bfloat16* il,
                                             int node, int lane, float4 v) {
    int b = node >> 7, r = node & 127;
    int col = lane << 2;
    uint32_t byte = a_img_byte(b, col >> 6, r, col & 63);
    __nv_bfloat16 h0 = __float2bfloat16(v.x), h1 = __float2bfloat16(v.y);
    __nv_bfloat16 h2 = __float2bfloat16(v.z), h3 = __float2bfloat16(v.w);
    __nv_bfloat162 hp0; hp0.x = h0; hp0.y = h1;
    __nv_bfloat162 hp1; hp1.x = h2; hp1.y = h3;
    __nv_bfloat162 lp0;
    lp0.x = __float2bfloat16(v.x - __bfloat162float(h0));
    lp0.y = __float2bfloat16(v.y - __bfloat162float(h1));
    __nv_bfloat162 lp1;
    lp1.x = __float2bfloat16(v.z - __bfloat162float(h2));
    lp1.y = __float2bfloat16(v.w - __bfloat162float(h3));
    char* ph = (char*)ih + byte;
    char* pl = (char*)il + byte;
    *(__nv_bfloat162*)(ph)     = hp0;
    *(__nv_bfloat162*)(ph + 4) = hp1;
    *(__nv_bfloat162*)(pl)     = lp0;
    *(__nv_bfloat162*)(pl + 4) = lp1;
}

// ---------------- CSR construction ----------------
__global__ void count_kernel(const int* __restrict__ dst, int* cnt, int E) {
    int e = blockIdx.x * blockDim.x + threadIdx.x;
    if (e < E) atomicAdd(&cnt[dst[e]], 1);
}

__global__ void scan_kernel(const int* __restrict__ cnt, int* off, int* cur, int N) {
    __shared__ int part[1024];
    int t = threadIdx.x;
    int chunk = (N + 1023) / 1024;
    int s = t * chunk;
    int e = min(s + chunk, N);
    int sum = 0;
    for (int i = s; i < e; ++i) sum += cnt[i];
    part[t] = sum;
    __syncthreads();
    for (int d = 1; d < 1024; d <<= 1) {
        int v = (t >= d) ? part[t - d] : 0;
        __syncthreads();
        part[t] += v;
        __syncthreads();
    }
    int run = (t == 0) ? 0 : part[t - 1];
    for (int i = s; i < e; ++i) {
        off[i] = run;
        cur[i] = run;
        run += cnt[i];
    }
    if (t == 1023) off[N] = part[1023];
}

__global__ void fill_kernel(const int* __restrict__ src, const int* __restrict__ dst,
                            int* cur, int* out, int E) {
    int e = blockIdx.x * blockDim.x + threadIdx.x;
    if (e < E) {
        int d = dst[e];
        int pos = atomicAdd(&cur[d], 1);
        out[pos] = src[e];
    }
}

// ---------------- aggregation: warp-per-node CSR mean -> bf16 hi/lo image --
__global__ __launch_bounds__(256) void agg_kernel(
    const float* __restrict__ h,
    __nv_bfloat16* __restrict__ img_h, __nv_bfloat16* __restrict__ img_l,
    const int* __restrict__ off, const int* __restrict__ srcs, int N)
{
    int gw = (blockIdx.x * 256 + threadIdx.x) >> 5;
    int lane = threadIdx.x & 31;
    if (gw >= N) return;

    int s = __ldg(&off[gw]);
    int e = __ldg(&off[gw + 1]);

    float4 acc = make_float4(0.f, 0.f, 0.f, 0.f);
    int k = s;
    for (; k + 4 <= e; k += 4) {
        int u0 = __ldg(&srcs[k]);
        int u1 = __ldg(&srcs[k + 1]);
        int u2 = __ldg(&srcs[k + 2]);
        int u3 = __ldg(&srcs[k + 3]);
        float4 a = __ldg((const float4*)(h + (size_t)u0 * D + lane * 4));
        float4 b = __ldg((const float4*)(h + (size_t)u1 * D + lane * 4));
        float4 c = __ldg((const float4*)(h + (size_t)u2 * D + lane * 4));
        float4 d = __ldg((const float4*)(h + (size_t)u3 * D + lane * 4));
        acc.x += (a.x + b.x) + (c.x + d.x);
        acc.y += (a.y + b.y) + (c.y + d.y);
        acc.z += (a.z + b.z) + (c.z + d.z);
        acc.w += (a.w + b.w) + (c.w + d.w);
    }
    for (; k < e; ++k) {
        int u = __ldg(&srcs[k]);
        float4 a = __ldg((const float4*)(h + (size_t)u * D + lane * 4));
        acc.x += a.x; acc.y += a.y; acc.z += a.z; acc.w += a.w;
    }
    float ic = 1.0f / (float)max(e - s, 1);
    acc.x *= ic; acc.y *= ic; acc.z *= ic; acc.w *= ic;
    store_a_quad(img_h, img_l, gw, lane, acc);
}

// ---------------- x -> bf16 hi/lo image ----------------
__global__ void prep_x_kernel(const float* __restrict__ x,
                              __nv_bfloat16* __restrict__ ih,
                              __nv_bfloat16* __restrict__ il, int N)
{
    int i = blockIdx.x * 256 + threadIdx.x;
    int node = i >> 5;
    int lane = i & 31;
    if (node >= N) return;
    float4 v = __ldg((const float4*)(x + (size_t)node * D + lane * 4));
    store_a_quad(ih, il, node, lane, v);
}

// ---------------- weight prep (all 6 matrices in one launch) ---------------
// Image layout (per k-chunk of 64): byte = (k>>6)*16384 + (k&63)*256
//                                        + (((n>>3) ^ (k&7)) << 4) + (n&7)*2
__global__ void prep_w_kernel(const float* W0, const float* W1, const float* W2,
                              const float* W3, const float* W4, const float* W5,
                              __nv_bfloat16* __restrict__ wimg)
{
    int gi = blockIdx.x * 256 + threadIdx.x;
    if (gi >= 6 * 16384) return;
    int m = gi >> 14;
    int i = gi & 16383;
    const float* Ws[6] = {W0, W1, W2, W3, W4, W5};
    int k = i >> 7;
    int n = i & 127;
    float x = __ldg(Ws[m] + k * 128 + n);
    __nv_bfloat16 h = __float2bfloat16(x);
    float l = x - __bfloat162float(h);
    uint32_t byte = (uint32_t)(k >> 6) * 16384u + (uint32_t)(k & 63) * 256u
                  + ((uint32_t)((n >> 3) ^ (k & 7)) << 4) + (uint32_t)(n & 7) * 2u;
    __nv_bfloat16* hi = wimg + (size_t)(2 * m) * 16384;
    __nv_bfloat16* lo = hi + 16384;
    hi[byte >> 1] = h;
    lo[byte >> 1] = __float2bfloat16(l);
}

// ---------------- HMMA GEMM: relu([mean|h] @ [Wl;Wr] + b), bf16 split-3 ----
// CTA: 128 rows x 128 cols, K=256 in 4 chunks of 64. 8 warps, warp = 32x64.
// All staging is pure cp.async 16B copies from pre-swizzled images.
#define GT 256
#define SM_AHI 0
#define SM_ALO 16384
#define SM_WHI 32768
#define SM_WLO 49152
#define SM_TOT 65536

__global__ __launch_bounds__(GT, 2) void gemm_mma_kernel(
    const __nv_bfloat16* __restrict__ mh, const __nv_bfloat16* __restrict__ ml,
    const __nv_bfloat16* __restrict__ hh, const __nv_bfloat16* __restrict__ hl,
    float* __restrict__ h_out,
    const __nv_bfloat16* __restrict__ wlhi, const __nv_bfloat16* __restrict__ wllo,
    const __nv_bfloat16* __restrict__ wrhi, const __nv_bfloat16* __restrict__ wrlo,
    const float* __restrict__ bias,
    __nv_bfloat16* __restrict__ oih, __nv_bfloat16* __restrict__ oil,
    int write_img, int N)
{
    extern __shared__ char smem[];
    const uint32_t sb = smem_u32(smem);
    const int t = threadIdx.x;
    const int lane = t & 31;
    const int w = t >> 5;
    const int wrow = (w & 3) * 32;
    const int wcol = (w >> 2) * 64;
    const int row0 = blockIdx.x * 128;

    const __nv_bfloat16* aih[2] = {mh, hh};
    const __nv_bfloat16* ail[2] = {ml, hl};
    const __nv_bfloat16* whis[2] = {wlhi, wrhi};
    const __nv_bfloat16* wlos[2] = {wllo, wrlo};

    float C[64];
#pragma unroll
    for (int i = 0; i < 64; ++i) C[i] = 0.f;

    const int rsel = (lane & 7) + ((lane >> 3) & 1) * 8;
    const int usel = lane >> 4;

    for (int chunk = 0; chunk < 4; ++chunk) {
        const int mat = chunk >> 1;   // 0: mean@Wl, 1: h@Wr
        const int kh  = chunk & 1;

        // ---- stage A + W chunks: 4 x 16KB pure cp.async copies ----
        const char* ah = (const char*)aih[mat] + (size_t)blockIdx.x * 32768 + kh * 16384;
        const char* al = (const char*)ail[mat] + (size_t)blockIdx.x * 32768 + kh * 16384;
        const char* wh = (const char*)whis[mat] + kh * 16384;
        const char* wl = (const char*)wlos[mat] + kh * 16384;
        for (int i = t; i < 1024; i += GT) {
            uint32_t o = (uint32_t)i << 4;
            cp16(sb + SM_AHI + o, ah + o);
            cp16(sb + SM_ALO + o, al + o);
            cp16(sb + SM_WHI + o, wh + o);
            cp16(sb + SM_WLO + o, wl + o);
        }
        asm volatile("cp.async.commit_group;" ::: "memory");
        asm volatile("cp.async.wait_group 0;" ::: "memory");
        __syncthreads();

        // ---- compute: 4 k-steps of 16 ----
#pragma unroll
        for (int ks = 0; ks < 4; ++ks) {
            const int k0 = ks * 16;
            uint32_t ahf[2][4], alf[2][4];
#pragma unroll
            for (int mf = 0; mf < 2; ++mf) {
                int row = wrow + mf * 16 + rsel;
                uint32_t unit = (uint32_t)(((k0 >> 3) + usel) ^ (lane & 7));
                uint32_t aaddr = sb + SM_AHI + (uint32_t)row * 128u + (unit << 4);
                ldsm_x4(ahf[mf], aaddr);
                ldsm_x4(alf[mf], aaddr + 16384u);
            }
#pragma unroll
            for (int nq = 0; nq < 4; ++nq) {
                const int n0 = wcol + nq * 16;
                int krow = k0 + rsel;
                uint32_t unit = (uint32_t)(((n0 >> 3) + usel) ^ (lane & 7));
                uint32_t baddr = sb + SM_WHI + (uint32_t)krow * 256u + (unit << 4);
                uint32_t bh[4], bl[4];
                ldsm_x4_t(bh, baddr);
                ldsm_x4_t(bl, baddr + 16384u);
#pragma unroll
                for (int mf = 0; mf < 2; ++mf) {
                    float* c0 = &C[((mf * 8 + nq * 2) << 2)];
                    float* c1 = &C[((mf * 8 + nq * 2 + 1) << 2)];
                    mma_bf16(c0, ahf[mf], bh);
                    mma_bf16(c0, ahf[mf], bl);
                    mma_bf16(c0, alf[mf], bh);
                    mma_bf16(c1, ahf[mf], bh + 2);
                    mma_bf16(c1, ahf[mf], bl + 2);
                    mma_bf16(c1, alf[mf], bh + 2);
                }
            }
        }
        __syncthreads();
    }

    // ---- epilogue: bias + relu + fp32 store + (optional) bf16 image store ----
#pragma unroll
    for (int mf = 0; mf < 2; ++mf) {
        int rloc = wrow + mf * 16 + (lane >> 2);
        int rlo = row0 + rloc;
#pragma unroll
        for (int nf = 0; nf < 8; ++nf) {
            int col = wcol + nf * 8 + (lane & 3) * 2;
            float b0 = __ldg(bias + col);
            float b1 = __ldg(bias + col + 1);
            const float* c = &C[((mf * 8 + nf) << 2)];
            float v0 = fmaxf(c[0] + b0, 0.f);
            float v1 = fmaxf(c[1] + b1, 0.f);
            float v2 = fmaxf(c[2] + b0, 0.f);
            float v3 = fmaxf(c[3] + b1, 0.f);
            if (rlo < N) {
                *(float2*)(h_out + (size_t)rlo * D + col) = make_float2(v0, v1);
                if (write_img) {
                    uint32_t byte = a_img_byte(blockIdx.x, col >> 6, rloc, col & 63);
                    __nv_bfloat16 h0 = __float2bfloat16(v0), h1 = __float2bfloat16(v1);
                    __nv_bfloat162 hp; hp.x = h0; hp.y = h1;
                    __nv_bfloat162 lp;
                    lp.x = __float2bfloat16(v0 - __bfloat162float(h0));
                    lp.y = __float2bfloat16(v1 - __bfloat162float(h1));
                    *(__nv_bfloat162*)((char*)oih + byte) = hp;
                    *(__nv_bfloat162*)((char*)oil + byte) = lp;
                }
            }
            int rhi = rlo + 8;
            if (rhi < N) {
                *(float2*)(h_out + (size_t)rhi * D + col) = make_float2(v2, v3);
                if (write_img) {
                    uint32_t byte = a_img_byte(blockIdx.x, col >> 6, rloc + 8, col & 63);
                    __nv_bfloat16 h2 = __float2bfloat16(v2), h3 = __float2bfloat16(v3);
                    __nv_bfloat162 hp; hp.x = h2; hp.y = h3;
                    __nv_bfloat162 lp;
                    lp.x = __float2bfloat16(v2 - __bfloat162float(h2));
                    lp.y = __float2bfloat16(v3 - __bfloat162float(h3));
                    *(__nv_bfloat162*)((char*)oih + byte) = hp;
                    *(__nv_bfloat162*)((char*)oil + byte) = lp;
                }
            }
        }
    }
}

// ---------------- pooled sum (sorted batch) + sigmoid head -----------------
__global__ void pool_head_kernel(const float* __restrict__ h, const int* __restrict__ batch,
                                 const float* __restrict__ Wro, const float* __restrict__ bro,
                                 float* __restrict__ out, int N)
{
    __shared__ int bounds[2];
    __shared__ float red[4];
    int g = blockIdx.x;
    int t = threadIdx.x;

    if (t < 2) {
        int target = g + t;
        int lo = 0, hi = N;
        while (lo < hi) {
            int mid = (lo + hi) >> 1;
            if (batch[mid] < target) lo = mid + 1; else hi = mid;
        }
        bounds[t] = lo;
    }
    __syncthreads();
    int s = bounds[0], e = bounds[1];

    float sum = 0.0f;
    for (int v = s; v < e; ++v) sum += h[(size_t)v * D + t];
    float val = sum * __ldg(&Wro[t]);
#pragma unroll
    for (int o = 16; o > 0; o >>= 1) val += __shfl_xor_sync(0xffffffff, val, o);
    if ((t & 31) == 0) red[t >> 5] = val;
    __syncthreads();
    if (t == 0) {
        float z = red[0] + red[1] + red[2] + red[3] + __ldg(bro);
        out[g] = 1.0f / (1.0f + expf(-z));
    }
}

// ---------------- launcher ----------------
extern "C" void kernel_launch(void* const* d_in, const int* in_sizes, int n_in,
                              void* d_out, int out_size)
{
    const float* x     = (const float*)d_in[0];
    const int*   ei    = (const int*)d_in[1];
    const int*   batch = (const int*)d_in[2];
    const float* Wl1 = (const float*)d_in[3];
    const float* Wr1 = (const float*)d_in[4];
    const float* b1  = (const float*)d_in[5];
    const float* Wl2 = (const float*)d_in[6];
    const float* Wr2 = (const float*)d_in[7];
    const float* b2  = (const float*)d_in[8];
    const float* Wl3 = (const float*)d_in[9];
    const float* Wr3 = (const float*)d_in[10];
    const float* b3  = (const float*)d_in[11];
    const float* Wro = (const float*)d_in[12];
    const float* bro = (const float*)d_in[13];
    float* out = (float*)d_out;

    int N = in_sizes[0] / D;
    int E = in_sizes[1] / 2;
    int G = out_size;

    float *h0, *h1;
    int *cnt, *off, *cur, *srcs;
    __nv_bfloat16 *wimg, *mih, *mil, *xih, *xil, *yih, *yil;
    cudaGetSymbolAddress((void**)&h0,   g_h0);
    cudaGetSymbolAddress((void**)&h1,   g_h1);
    cudaGetSymbolAddress((void**)&cnt,  g_cnt);
    cudaGetSymbolAddress((void**)&off,  g_off);
    cudaGetSymbolAddress((void**)&cur,  g_cur);
    cudaGetSymbolAddress((void**)&srcs, g_src);
    cudaGetSymbolAddress((void**)&wimg, g_wimg);
    cudaGetSymbolAddress((void**)&mih,  g_mimg_h);
    cudaGetSymbolAddress((void**)&mil,  g_mimg_l);
    cudaGetSymbolAddress((void**)&xih,  g_ximg_h);
    cudaGetSymbolAddress((void**)&xil,  g_ximg_l);
    cudaGetSymbolAddress((void**)&yih,  g_yimg_h);
    cudaGetSymbolAddress((void**)&yil,  g_yimg_l);

    const int* src_arr = ei;
    const int* dst_arr = ei + E;

    // prep: weights (one launch) + x image
    prep_w_kernel<<<(6 * 16384 + 255) / 256, 256>>>(Wl1, Wr1, Wl2, Wr2, Wl3, Wr3, wimg);
    prep_x_kernel<<<(N * 32 + 255) / 256, 256>>>(x, xih, xil, N);

    // CSR build
    cudaMemsetAsync(cnt, 0, (size_t)N * sizeof(int));
    count_kernel<<<(E + 255) / 256, 256>>>(dst_arr, cnt, E);
    scan_kernel<<<1, 1024>>>(cnt, off, cur, N);
    fill_kernel<<<(E + 255) / 256, 256>>>(src_arr, dst_arr, cur, srcs, E);

    cudaFuncSetAttribute((const void*)gemm_mma_kernel,
                         cudaFuncAttributeMaxDynamicSharedMemorySize, SM_TOT);
    int gblocks = (N + 127) / 128;
    int ablocks = (N * 32 + 255) / 256;

    __nv_bfloat16* im = wimg;
    // layer 1: A-h from x image, write y image
    agg_kernel<<<ablocks, 256>>>(x, mih, mil, off, srcs, N);
    gemm_mma_kernel<<<gblocks, GT, SM_TOT>>>(mih, mil, xih, xil, h0,
        im + 0 * 16384, im + 1 * 16384, im + 2 * 16384, im + 3 * 16384, b1,
        yih, yil, 1, N);
    // layer 2: A-h from y image, write x image (x no longer needed)
    agg_kernel<<<ablocks, 256>>>(h0, mih, mil, off, srcs, N);
    gemm_mma_kernel<<<gblocks, GT, SM_TOT>>>(mih, mil, yih, yil, h1,
        im + 4 * 16384, im + 5 * 16384, im + 6 * 16384, im + 7 * 16384, b2,
        xih, xil, 1, N);
    // layer 3: A-h from x image, no image write
    agg_kernel<<<ablocks, 256>>>(h1, mih, mil, off, srcs, N);
    gemm_mma_kernel<<<gblocks, GT, SM_TOT>>>(mih, mil, xih, xil, h0,
        im + 8 * 16384, im + 9 * 16384, im + 10 * 16384, im + 11 * 16384, b3,
        yih, yil, 0, N);

    // pooling + head
    pool_head_kernel<<<G, D>>>(h0, batch, Wro, bro, out, N);
}

// round 10
// speedup vs baseline: 3.0954x; 1.3884x over previous
#include <cuda_runtime.h>
#include <cuda_bf16.h>
#include <math.h>
#include <stdint.h>

#define D 128
#define MAXN 100000
#define MAXE 600000
#define NBLK 782   // ceil(MAXN/128)

// ---------------- static device scratch (no allocs allowed) ----------------
__device__ float g_h0[(size_t)MAXN * D];
__device__ float g_h1[(size_t)MAXN * D];
__device__ int   g_cnt[MAXN];
__device__ int   g_off[MAXN + 1];
__device__ int   g_cur[MAXN];
__device__ int   g_src[MAXE];
__device__ int   g_bsum[1024];
// 12 pre-swizzled weight images: (3 layers x {Wl,Wr} x {hi,lo}), each 128k x 128n bf16
__device__ __nv_bfloat16 g_wimg[12 * 16384];
// A-operand images (pre-swizzled, per 128-row block: 128 rows x 2 k-halves x 128B)
__device__ __nv_bfloat16 g_mimg_h[(size_t)NBLK * 16384];
__device__ __nv_bfloat16 g_mimg_l[(size_t)NBLK * 16384];
__device__ __nv_bfloat16 g_ximg_h[(size_t)NBLK * 16384];
__device__ __nv_bfloat16 g_ximg_l[(size_t)NBLK * 16384];
__device__ __nv_bfloat16 g_yimg_h[(size_t)NBLK * 16384];
__device__ __nv_bfloat16 g_yimg_l[(size_t)NBLK * 16384];

// ---------------- helpers ----------------
__device__ __forceinline__ uint32_t smem_u32(const void* p) {
    uint32_t a;
    asm("{ .reg .u64 t; cvta.to.shared.u64 t, %1; cvt.u32.u64 %0, t; }" : "=r"(a) : "l"(p));
    return a;
}
__device__ __forceinline__ void cp16(uint32_t s, const void* g) {
    asm volatile("cp.async.cg.shared.global [%0], [%1], 16;" :: "r"(s), "l"(g));
}
__device__ __forceinline__ void ldsm_x4(uint32_t* r, uint32_t addr) {
    asm volatile("ldmatrix.sync.aligned.m8n8.x4.shared.b16 {%0,%1,%2,%3}, [%4];"
                 : "=r"(r[0]), "=r"(r[1]), "=r"(r[2]), "=r"(r[3]) : "r"(addr));
}
__device__ __forceinline__ void ldsm_x4_t(uint32_t* r, uint32_t addr) {
    asm volatile("ldmatrix.sync.aligned.m8n8.x4.trans.shared.b16 {%0,%1,%2,%3}, [%4];"
                 : "=r"(r[0]), "=r"(r[1]), "=r"(r[2]), "=r"(r[3]) : "r"(addr));
}
__device__ __forceinline__ void mma_bf16(float* c, const uint32_t* a, const uint32_t* b) {
    asm volatile(
        "mma.sync.aligned.m16n8k16.row.col.f32.bf16.bf16.f32 "
        "{%0,%1,%2,%3}, {%4,%5,%6,%7}, {%8,%9}, {%0,%1,%2,%3};"
        : "+f"(c[0]), "+f"(c[1]), "+f"(c[2]), "+f"(c[3])
        : "r"(a[0]), "r"(a[1]), "r"(a[2]), "r"(a[3]), "r"(b[0]), "r"(b[1]));
}

// A-image byte offset: block, k-half, row (0..127), k within half (0..63)
__device__ __forceinline__ uint32_t a_img_byte(int b, int kh, int r, int kp) {
    return (uint32_t)b * 32768u + (uint32_t)kh * 16384u + (uint32_t)r * 128u
         + ((uint32_t)((kp >> 3) ^ (r & 7)) << 4) + ((uint32_t)(kp & 7) << 1);
}

// store 4 consecutive cols (col0 = 4*lane) of a node as bf16 hi/lo pairs
__device__ __forceinline__ void store_a_quad(__nv_bfloat16* ih, __nv_bfloat16* il,
                                             int node, int lane, float4 v) {
    int b = node >> 7, r = node & 127;
    int col = lane << 2;
    uint32_t byte = a_img_byte(b, col >> 6, r, col & 63);
    __nv_bfloat16 h0 = __float2bfloat16(v.x), h1 = __float2bfloat16(v.y);
    __nv_bfloat16 h2 = __float2bfloat16(v.z), h3 = __float2bfloat16(v.w);
    __nv_bfloat162 hp0; hp0.x = h0; hp0.y = h1;
    __nv_bfloat162 hp1; hp1.x = h2; hp1.y = h3;
    __nv_bfloat162 lp0;
    lp0.x = __float2bfloat16(v.x - __bfloat162float(h0));
    lp0.y = __float2bfloat16(v.y - __bfloat162float(h1));
    __nv_bfloat162 lp1;
    lp1.x = __float2bfloat16(v.z - __bfloat162float(h2));
    lp1.y = __float2bfloat16(v.w - __bfloat162float(h3));
    char* ph = (char*)ih + byte;
    char* pl = (char*)il + byte;
    *(__nv_bfloat162*)(ph)     = hp0;
    *(__nv_bfloat162*)(ph + 4) = hp1;
    *(__nv_bfloat162*)(pl)     = lp0;
    *(__nv_bfloat162*)(pl + 4) = lp1;
}

// ---------------- CSR construction ----------------
__global__ void count_kernel(const int* __restrict__ dst, int* cnt, int E) {
    int e = blockIdx.x * blockDim.x + threadIdx.x;
    if (e < E) atomicAdd(&cnt[dst[e]], 1);
}

// phase 1: per-1024-block sums
__global__ void bsum_kernel(const int* __restrict__ cnt, int* bsum, int N) {
    __shared__ int red[32];
    int i = blockIdx.x * 1024 + threadIdx.x;
    int v = (i < N) ? cnt[i] : 0;
#pragma unroll
    for (int o = 16; o > 0; o >>= 1) v += __shfl_down_sync(0xffffffff, v, o);
    if ((threadIdx.x & 31) == 0) red[threadIdx.x >> 5] = v;
    __syncthreads();
    if (threadIdx.x < 32) {
        int s = red[threadIdx.x];
#pragma unroll
        for (int o = 16; o > 0; o >>= 1) s += __shfl_down_sync(0xffffffff, s, o);
        if (threadIdx.x == 0) bsum[blockIdx.x] = s;
    }
}

// phase 2: single small block scans the (<=1024) block sums -> exclusive
__global__ void scan_bsum_kernel(int* bsum, int* off, int nb, int N) {
    __shared__ int s[1024];
    int t = threadIdx.x;
    int v = (t < nb) ? bsum[t] : 0;
    s[t] = v;
    __syncthreads();
    for (int d = 1; d < 1024; d <<= 1) {
        int x = (t >= d) ? s[t - d] : 0;
        __syncthreads();
        s[t] += x;
        __syncthreads();
    }
    if (t < nb) bsum[t] = s[t] - v;       // exclusive
    if (t == 1023) off[N] = s[1023];      // total edge count
}

// phase 3: per-block Hillis-Steele over 1024 + block offset
__global__ void scan_final_kernel(const int* __restrict__ cnt, const int* __restrict__ bsum,
                                  int* off, int* cur, int N) {
    __shared__ int s[1024];
    int t = threadIdx.x;
    int i = blockIdx.x * 1024 + t;
    int v = (i < N) ? cnt[i] : 0;
    s[t] = v;
    __syncthreads();
    for (int d = 1; d < 1024; d <<= 1) {
        int x = (t >= d) ? s[t - d] : 0;
        __syncthreads();
        s[t] += x;
        __syncthreads();
    }
    if (i < N) {
        int excl = s[t] - v + bsum[blockIdx.x];
        off[i] = excl;
        cur[i] = excl;
    }
}

__global__ void fill_kernel(const int* __restrict__ src, const int* __restrict__ dst,
                            int* cur, int* out, int E) {
    int e = blockIdx.x * blockDim.x + threadIdx.x;
    if (e < E) {
        int d = dst[e];
        int pos = atomicAdd(&cur[d], 1);
        out[pos] = src[e];
    }
}

// ---------------- aggregation: warp-per-node CSR mean -> bf16 hi/lo image --
__global__ __launch_bounds__(256) void agg_kernel(
    const float* __restrict__ h,
    __nv_bfloat16* __restrict__ img_h, __nv_bfloat16* __restrict__ img_l,
    const int* __restrict__ off, const int* __restrict__ srcs, int N)
{
    int gw = (blockIdx.x * 256 + threadIdx.x) >> 5;
    int lane = threadIdx.x & 31;
    if (gw >= N) return;

    int s = __ldg(&off[gw]);
    int e = __ldg(&off[gw + 1]);

    float4 acc = make_float4(0.f, 0.f, 0.f, 0.f);
    int k = s;
    for (; k + 4 <= e; k += 4) {
        int u0 = __ldg(&srcs[k]);
        int u1 = __ldg(&srcs[k + 1]);
        int u2 = __ldg(&srcs[k + 2]);
        int u3 = __ldg(&srcs[k + 3]);
        float4 a = __ldg((const float4*)(h + (size_t)u0 * D + lane * 4));
        float4 b = __ldg((const float4*)(h + (size_t)u1 * D + lane * 4));
        float4 c = __ldg((const float4*)(h + (size_t)u2 * D + lane * 4));
        float4 d = __ldg((const float4*)(h + (size_t)u3 * D + lane * 4));
        acc.x += (a.x + b.x) + (c.x + d.x);
        acc.y += (a.y + b.y) + (c.y + d.y);
        acc.z += (a.z + b.z) + (c.z + d.z);
        acc.w += (a.w + b.w) + (c.w + d.w);
    }
    for (; k < e; ++k) {
        int u = __ldg(&srcs[k]);
        float4 a = __ldg((const float4*)(h + (size_t)u * D + lane * 4));
        acc.x += a.x; acc.y += a.y; acc.z += a.z; acc.w += a.w;
    }
    float ic = 1.0f / (float)max(e - s, 1);
    acc.x *= ic; acc.y *= ic; acc.z *= ic; acc.w *= ic;
    store_a_quad(img_h, img_l, gw, lane, acc);
}

// ---------------- x -> bf16 hi/lo image ----------------
__global__ void prep_x_kernel(const float* __restrict__ x,
                              __nv_bfloat16* __restrict__ ih,
                              __nv_bfloat16* __restrict__ il, int N)
{
    int i = blockIdx.x * 256 + threadIdx.x;
    int node = i >> 5;
    int lane = i & 31;
    if (node >= N) return;
    float4 v = __ldg((const float4*)(x + (size_t)node * D + lane * 4));
    store_a_quad(ih, il, node, lane, v);
}

// ---------------- weight prep (all 6 matrices in one launch) ---------------
__global__ void prep_w_kernel(const float* W0, const float* W1, const float* W2,
                              const float* W3, const float* W4, const float* W5,
                              __nv_bfloat16* __restrict__ wimg)
{
    int gi = blockIdx.x * 256 + threadIdx.x;
    if (gi >= 6 * 16384) return;
    int m = gi >> 14;
    int i = gi & 16383;
    const float* Ws[6] = {W0, W1, W2, W3, W4, W5};
    int k = i >> 7;
    int n = i & 127;
    float x = __ldg(Ws[m] + k * 128 + n);
    __nv_bfloat16 h = __float2bfloat16(x);
    float l = x - __bfloat162float(h);
    uint32_t byte = (uint32_t)(k >> 6) * 16384u + (uint32_t)(k & 63) * 256u
                  + ((uint32_t)((n >> 3) ^ (k & 7)) << 4) + (uint32_t)(n & 7) * 2u;
    __nv_bfloat16* hi = wimg + (size_t)(2 * m) * 16384;
    __nv_bfloat16* lo = hi + 16384;
    hi[byte >> 1] = h;
    lo[byte >> 1] = __float2bfloat16(l);
}

// ---------------- HMMA GEMM: relu([mean|h] @ [Wl;Wr] + b), bf16 split-3 ----
#define GT 256
#define SM_AHI 0
#define SM_ALO 16384
#define SM_WHI 32768
#define SM_WLO 49152
#define SM_TOT 65536

__global__ __launch_bounds__(GT, 2) void gemm_mma_kernel(
    const __nv_bfloat16* __restrict__ mh, const __nv_bfloat16* __restrict__ ml,
    const __nv_bfloat16* __restrict__ hh, const __nv_bfloat16* __restrict__ hl,
    float* __restrict__ h_out,
    const __nv_bfloat16* __restrict__ wlhi, const __nv_bfloat16* __restrict__ wllo,
    const __nv_bfloat16* __restrict__ wrhi, const __nv_bfloat16* __restrict__ wrlo,
    const float* __restrict__ bias,
    __nv_bfloat16* __restrict__ oih, __nv_bfloat16* __restrict__ oil,
    int write_img, int N)
{
    extern __shared__ char smem[];
    const uint32_t sb = smem_u32(smem);
    const int t = threadIdx.x;
    const int lane = t & 31;
    const int w = t >> 5;
    const int wrow = (w & 3) * 32;
    const int wcol = (w >> 2) * 64;
    const int row0 = blockIdx.x * 128;

    const __nv_bfloat16* aih[2] = {mh, hh};
    const __nv_bfloat16* ail[2] = {ml, hl};
    const __nv_bfloat16* whis[2] = {wlhi, wrhi};
    const __nv_bfloat16* wlos[2] = {wllo, wrlo};

    float C[64];
#pragma unroll
    for (int i = 0; i < 64; ++i) C[i] = 0.f;

    const int rsel = (lane & 7) + ((lane >> 3) & 1) * 8;
    const int usel = lane >> 4;

    for (int chunk = 0; chunk < 4; ++chunk) {
        const int mat = chunk >> 1;   // 0: mean@Wl, 1: h@Wr
        const int kh  = chunk & 1;

        // ---- stage A + W chunks: 4 x 16KB pure cp.async copies ----
        const char* ah = (const char*)aih[mat] + (size_t)blockIdx.x * 32768 + kh * 16384;
        const char* al = (const char*)ail[mat] + (size_t)blockIdx.x * 32768 + kh * 16384;
        const char* wh = (const char*)whis[mat] + kh * 16384;
        const char* wl = (const char*)wlos[mat] + kh * 16384;
        for (int i = t; i < 1024; i += GT) {
            uint32_t o = (uint32_t)i << 4;
            cp16(sb + SM_AHI + o, ah + o);
            cp16(sb + SM_ALO + o, al + o);
            cp16(sb + SM_WHI + o, wh + o);
            cp16(sb + SM_WLO + o, wl + o);
        }
        asm volatile("cp.async.commit_group;" ::: "memory");
        asm volatile("cp.async.wait_group 0;" ::: "memory");
        __syncthreads();

        // ---- compute: 4 k-steps of 16 ----
#pragma unroll
        for (int ks = 0; ks < 4; ++ks) {
            const int k0 = ks * 16;
            uint32_t ahf[2][4], alf[2][4];
#pragma unroll
            for (int mf = 0; mf < 2; ++mf) {
                int row = wrow + mf * 16 + rsel;
                uint32_t unit = (uint32_t)(((k0 >> 3) + usel) ^ (lane & 7));
                uint32_t aaddr = sb + SM_AHI + (uint32_t)row * 128u + (unit << 4);
                ldsm_x4(ahf[mf], aaddr);
                ldsm_x4(alf[mf], aaddr + 16384u);
            }
#pragma unroll
            for (int nq = 0; nq < 4; ++nq) {
                const int n0 = wcol + nq * 16;
                int krow = k0 + rsel;
                uint32_t unit = (uint32_t)(((n0 >> 3) + usel) ^ (lane & 7));
                uint32_t baddr = sb + SM_WHI + (uint32_t)krow * 256u + (unit << 4);
                uint32_t bh[4], bl[4];
                ldsm_x4_t(bh, baddr);
                ldsm_x4_t(bl, baddr + 16384u);
#pragma unroll
                for (int mf = 0; mf < 2; ++mf) {
                    float* c0 = &C[((mf * 8 + nq * 2) << 2)];
                    float* c1 = &C[((mf * 8 + nq * 2 + 1) << 2)];
                    mma_bf16(c0, ahf[mf], bh);
                    mma_bf16(c0, ahf[mf], bl);
                    mma_bf16(c0, alf[mf], bh);
                    mma_bf16(c1, ahf[mf], bh + 2);
                    mma_bf16(c1, ahf[mf], bl + 2);
                    mma_bf16(c1, alf[mf], bh + 2);
                }
            }
        }
        __syncthreads();
    }

    // ---- epilogue: bias + relu + fp32 store + (optional) bf16 image store ----
#pragma unroll
    for (int mf = 0; mf < 2; ++mf) {
        int rloc = wrow + mf * 16 + (lane >> 2);
        int rlo = row0 + rloc;
#pragma unroll
        for (int nf = 0; nf < 8; ++nf) {
            int col = wcol + nf * 8 + (lane & 3) * 2;
            float b0 = __ldg(bias + col);
            float b1 = __ldg(bias + col + 1);
            const float* c = &C[((mf * 8 + nf) << 2)];
            float v0 = fmaxf(c[0] + b0, 0.f);
            float v1 = fmaxf(c[1] + b1, 0.f);
            float v2 = fmaxf(c[2] + b0, 0.f);
            float v3 = fmaxf(c[3] + b1, 0.f);
            if (rlo < N) {
                *(float2*)(h_out + (size_t)rlo * D + col) = make_float2(v0, v1);
                if (write_img) {
                    uint32_t byte = a_img_byte(blockIdx.x, col >> 6, rloc, col & 63);
                    __nv_bfloat16 h0 = __float2bfloat16(v0), h1 = __float2bfloat16(v1);
                    __nv_bfloat162 hp; hp.x = h0; hp.y = h1;
                    __nv_bfloat162 lp;
                    lp.x = __float2bfloat16(v0 - __bfloat162float(h0));
                    lp.y = __float2bfloat16(v1 - __bfloat162float(h1));
                    *(__nv_bfloat162*)((char*)oih + byte) = hp;
                    *(__nv_bfloat162*)((char*)oil + byte) = lp;
                }
            }
            int rhi = rlo + 8;
            if (rhi < N) {
                *(float2*)(h_out + (size_t)rhi * D + col) = make_float2(v2, v3);
                if (write_img) {
                    uint32_t byte = a_img_byte(blockIdx.x, col >> 6, rloc + 8, col & 63);
                    __nv_bfloat16 h2 = __float2bfloat16(v2), h3 = __float2bfloat16(v3);
                    __nv_bfloat162 hp; hp.x = h2; hp.y = h3;
                    __nv_bfloat162 lp;
                    lp.x = __float2bfloat16(v2 - __bfloat162float(h2));
                    lp.y = __float2bfloat16(v3 - __bfloat162float(h3));
                    *(__nv_bfloat162*)((char*)oih + byte) = hp;
                    *(__nv_bfloat162*)((char*)oil + byte) = lp;
                }
            }
        }
    }
}

// ---------------- pooled sum (sorted batch) + sigmoid head -----------------
__global__ void pool_head_kernel(const float* __restrict__ h, const int* __restrict__ batch,
                                 const float* __restrict__ Wro, const float* __restrict__ bro,
                                 float* __restrict__ out, int N)
{
    __shared__ int bounds[2];
    __shared__ float red[4];
    int g = blockIdx.x;
    int t = threadIdx.x;

    if (t < 2) {
        int target = g + t;
        int lo = 0, hi = N;
        while (lo < hi) {
            int mid = (lo + hi) >> 1;
            if (batch[mid] < target) lo = mid + 1; else hi = mid;
        }
        bounds[t] = lo;
    }
    __syncthreads();
    int s = bounds[0], e = bounds[1];

    float sum = 0.0f;
    for (int v = s; v < e; ++v) sum += h[(size_t)v * D + t];
    float val = sum * __ldg(&Wro[t]);
#pragma unroll
    for (int o = 16; o > 0; o >>= 1) val += __shfl_xor_sync(0xffffffff, val, o);
    if ((t & 31) == 0) red[t >> 5] = val;
    __syncthreads();
    if (t == 0) {
        float z = red[0] + red[1] + red[2] + red[3] + __ldg(bro);
        out[g] = 1.0f / (1.0f + expf(-z));
    }
}

// ---------------- launcher ----------------
extern "C" void kernel_launch(void* const* d_in, const int* in_sizes, int n_in,
                              void* d_out, int out_size)
{
    const float* x     = (const float*)d_in[0];
    const int*   ei    = (const int*)d_in[1];
    const int*   batch = (const int*)d_in[2];
    const float* Wl1 = (const float*)d_in[3];
    const float* Wr1 = (const float*)d_in[4];
    const float* b1  = (const float*)d_in[5];
    const float* Wl2 = (const float*)d_in[6];
    const float* Wr2 = (const float*)d_in[7];
    const float* b2  = (const float*)d_in[8];
    const float* Wl3 = (const float*)d_in[9];
    const float* Wr3 = (const float*)d_in[10];
    const float* b3  = (const float*)d_in[11];
    const float* Wro = (const float*)d_in[12];
    const float* bro = (const float*)d_in[13];
    float* out = (float*)d_out;

    int N = in_sizes[0] / D;
    int E = in_sizes[1] / 2;
    int G = out_size;

    float *h0, *h1;
    int *cnt, *off, *cur, *srcs, *bsum;
    __nv_bfloat16 *wimg, *mih, *mil, *xih, *xil, *yih, *yil;
    cudaGetSymbolAddress((void**)&h0,   g_h0);
    cudaGetSymbolAddress((void**)&h1,   g_h1);
    cudaGetSymbolAddress((void**)&cnt,  g_cnt);
    cudaGetSymbolAddress((void**)&off,  g_off);
    cudaGetSymbolAddress((void**)&cur,  g_cur);
    cudaGetSymbolAddress((void**)&srcs, g_src);
    cudaGetSymbolAddress((void**)&bsum, g_bsum);
    cudaGetSymbolAddress((void**)&wimg, g_wimg);
    cudaGetSymbolAddress((void**)&mih,  g_mimg_h);
    cudaGetSymbolAddress((void**)&mil,  g_mimg_l);
    cudaGetSymbolAddress((void**)&xih,  g_ximg_h);
    cudaGetSymbolAddress((void**)&xil,  g_ximg_l);
    cudaGetSymbolAddress((void**)&yih,  g_yimg_h);
    cudaGetSymbolAddress((void**)&yil,  g_yimg_l);

    const int* src_arr = ei;
    const int* dst_arr = ei + E;

    // prep: weights (one launch) + x image
    prep_w_kernel<<<(6 * 16384 + 255) / 256, 256>>>(Wl1, Wr1, Wl2, Wr2, Wl3, Wr3, wimg);
    prep_x_kernel<<<(N * 32 + 255) / 256, 256>>>(x, xih, xil, N);

    // CSR build (parallel 3-phase scan)
    int nb = (N + 1023) / 1024;
    cudaMemsetAsync(cnt, 0, (size_t)N * sizeof(int));
    count_kernel<<<(E + 255) / 256, 256>>>(dst_arr, cnt, E);
    bsum_kernel<<<nb, 1024>>>(cnt, bsum, N);
    scan_bsum_kernel<<<1, 1024>>>(bsum, off, nb, N);
    scan_final_kernel<<<nb, 1024>>>(cnt, bsum, off, cur, N);
    fill_kernel<<<(E + 255) / 256, 256>>>(src_arr, dst_arr, cur, srcs, E);

    cudaFuncSetAttribute((const void*)gemm_mma_kernel,
                         cudaFuncAttributeMaxDynamicSharedMemorySize, SM_TOT);
    int gblocks = (N + 127) / 128;
    int ablocks = (N * 32 + 255) / 256;

    __nv_bfloat16* im = wimg;
    // layer 1: A-h from x image, write y image
    agg_kernel<<<ablocks, 256>>>(x, mih, mil, off, srcs, N);
    gemm_mma_kernel<<<gblocks, GT, SM_TOT>>>(mih, mil, xih, xil, h0,
        im + 0 * 16384, im + 1 * 16384, im + 2 * 16384, im + 3 * 16384, b1,
        yih, yil, 1, N);
    // layer 2: A-h from y image, write x image
    agg_kernel<<<ablocks, 256>>>(h0, mih, mil, off, srcs, N);
    gemm_mma_kernel<<<gblocks, GT, SM_TOT>>>(mih, mil, yih, yil, h1,
        im + 4 * 16384, im + 5 * 16384, im + 6 * 16384, im + 7 * 16384, b2,
        xih, xil, 1, N);
    // layer 3: A-h from x image, no image write
    agg_kernel<<<ablocks, 256>>>(h1, mih, mil, off, srcs, N);
    gemm_mma_kernel<<<gblocks, GT, SM_TOT>>>(mih, mil, xih, xil, h0,
        im + 8 * 16384, im + 9 * 16384, im + 10 * 16384, im + 11 * 16384, b3,
        yih, yil, 0, N);

    // pooling + head
    pool_head_kernel<<<G, D>>>(h0, batch, Wro, bro, out, N);
}